// round 17
// baseline (speedup 1.0000x reference)
#include <cuda_runtime.h>
#include <cuda_bf16.h>
#include <math_constants.h>
#include <cstdint>

// ============================================================================
// Problem constants
// ============================================================================
#define D        256
#define MROWS    32768
#define KCODES   8192
#define NTILE    64            // KCODES / 128
#define BM       128
#define BN       128
#define BK       16
#define TM       8
#define TN       8
#define NTHREADS 256

// dist kernel smem geometry (CTA 64 rows x 128 codes, BK=64, 2-stage ring)
#define SB       72                    // bf16 row stride (144 B, ldsm conflict-free)
#define ATILEB   (64 * SB * 2)         // 9216 B  : 64x64 zh tile
#define BTILEB   (128 * SB * 2)        // 18432 B : 128x64 eh tile
#define STAGEB   (ATILEB + BTILEB)     // 27648 B per stage
#define DIST_SMEM (2 * STAGEB)         // 55296 B -> 4 CTAs/SM (216KB <= 228KB)

// proj kernel smem: 2 stages x 2 tiles x 16 x 132 floats
#define PROJ_SMEM (2 * 2 * BK * (BM + 4) * 4)   // 67584 B

#define NLOSSBLK 4096

// ============================================================================
// Device scratch (no cudaMalloc allowed)
// ============================================================================
__device__ float          g_cn[KCODES];
__device__ float          g_part[NLOSSBLK];
__device__ unsigned int   g_cnt = 0;    // last-block counter (reset after use)
__device__ __nv_bfloat16  g_cbh[KCODES * D];
__device__ __nv_bfloat16  g_zh[MROWS * D];
__device__ float2         g_cv[(size_t)MROWS * NTILE];
__device__ int2           g_ci[(size_t)MROWS * NTILE];

// ============================================================================
// Helpers
// ============================================================================
__device__ __forceinline__ uint32_t smem_to_u32(const void* p) {
    uint32_t a;
    asm("{ .reg .u64 t; cvta.to.shared.u64 t, %1; cvt.u32.u64 %0, t; }"
        : "=r"(a) : "l"(p));
    return a;
}
__device__ __forceinline__ void cp16(uint32_t dst, const void* src) {
    asm volatile("cp.async.cg.shared.global [%0], [%1], 16;"
        :: "r"(dst), "l"(__cvta_generic_to_global(src)) : "memory");
}
__device__ __forceinline__ void ldsm_x4(uint32_t& r0, uint32_t& r1,
                                        uint32_t& r2, uint32_t& r3, uint32_t addr) {
    asm volatile("ldmatrix.sync.aligned.m8n8.x4.shared.b16 {%0,%1,%2,%3}, [%4];"
        : "=r"(r0), "=r"(r1), "=r"(r2), "=r"(r3) : "r"(addr));
}
__device__ __forceinline__ void mma16816(float* c, uint32_t a0, uint32_t a1,
                                         uint32_t a2, uint32_t a3,
                                         uint32_t b0, uint32_t b1) {
    asm volatile("mma.sync.aligned.m16n8k16.row.col.f32.bf16.bf16.f32 "
        "{%0,%1,%2,%3}, {%4,%5,%6,%7}, {%8,%9}, {%0,%1,%2,%3};"
        : "+f"(c[0]), "+f"(c[1]), "+f"(c[2]), "+f"(c[3])
        : "r"(a0), "r"(a1), "r"(a2), "r"(a3), "r"(b0), "r"(b1));
}
__device__ __forceinline__ void top2_merge(float& v0, int& i0, float& v1, int& i1,
                                           float w0, int j0, float w1, int j1) {
    if (w0 < v0) {
        if (v0 < w1) { v1 = v0; i1 = i0; } else { v1 = w1; i1 = j1; }
        v0 = w0; i0 = j0;
    } else if (w0 < v1) { v1 = w0; i1 = j0; }
}

// ============================================================================
// Kernel 1 (fused): blockIdx.y < 2  -> projection tile (exact fp32, pipelined,
//                   NUMERICS FROZEN) + bf16 hi split of z
//                   blockIdx.y == 2 -> codebook norms + bf16 hi split
// ============================================================================
__global__ __launch_bounds__(NTHREADS, 2)
void proj_cnsplit_kernel(const float* __restrict__ x, const float* __restrict__ W,
                         const float* __restrict__ b, const float* __restrict__ cb,
                         float* __restrict__ z) {
    if (blockIdx.y == 2) {
        int lane = threadIdx.x & 31;
        int w = threadIdx.x >> 5;
#pragma unroll
        for (int rr = 0; rr < 4; ++rr) {
            int row = blockIdx.x * 32 + w * 4 + rr;
            const float4* src = reinterpret_cast<const float4*>(cb + (size_t)row * D);
            __nv_bfloat162* dh = reinterpret_cast<__nv_bfloat162*>(g_cbh + (size_t)row * D);
            float s = 0.f;
#pragma unroll
            for (int p = 0; p < 2; ++p) {
                int qq = lane + p * 32;
                float4 v = src[qq];
                s += v.x * v.x + v.y * v.y + v.z * v.z + v.w * v.w;
                dh[qq * 2 + 0] = __nv_bfloat162(__float2bfloat16(v.x), __float2bfloat16(v.y));
                dh[qq * 2 + 1] = __nv_bfloat162(__float2bfloat16(v.z), __float2bfloat16(v.w));
            }
#pragma unroll
            for (int o = 16; o > 0; o >>= 1) s += __shfl_xor_sync(0xffffffffu, s, o);
            if (lane == 0) g_cn[row] = s;
        }
        return;
    }

    extern __shared__ __align__(16) float psm[];
    const int TS = BK * (BM + 4);          // 2112 floats per tile

    int tid = threadIdx.x;
    int tx = tid & 15, ty = tid >> 4;
    int rowBase = blockIdx.x * BM;
    int colBase = blockIdx.y * BN;

    int r0i = (tid + 0) >> 2, c40 = (tid + 0) & 3;
    int r1i = (tid + 256) >> 2, c41 = (tid + 256) & 3;

    auto gload = [&](float4& vx0, float4& vx1, float4& vw0, float4& vw1, int kt) {
        vx0 = *reinterpret_cast<const float4*>(x + (size_t)(rowBase + r0i) * D + kt * BK + c40 * 4);
        vx1 = *reinterpret_cast<const float4*>(x + (size_t)(rowBase + r1i) * D + kt * BK + c41 * 4);
        vw0 = *reinterpret_cast<const float4*>(W + (size_t)(colBase + r0i) * D + kt * BK + c40 * 4);
        vw1 = *reinterpret_cast<const float4*>(W + (size_t)(colBase + r1i) * D + kt * BK + c41 * 4);
    };
    auto sts = [&](int s, const float4& vx0, const float4& vx1,
                   const float4& vw0, const float4& vw1) {
        float* Xs = psm + s * 2 * TS;
        float* Ws = Xs + TS;
        Xs[(c40 * 4 + 0) * 132 + r0i] = vx0.x;
        Xs[(c40 * 4 + 1) * 132 + r0i] = vx0.y;
        Xs[(c40 * 4 + 2) * 132 + r0i] = vx0.z;
        Xs[(c40 * 4 + 3) * 132 + r0i] = vx0.w;
        Xs[(c41 * 4 + 0) * 132 + r1i] = vx1.x;
        Xs[(c41 * 4 + 1) * 132 + r1i] = vx1.y;
        Xs[(c41 * 4 + 2) * 132 + r1i] = vx1.z;
        Xs[(c41 * 4 + 3) * 132 + r1i] = vx1.w;
        Ws[(c40 * 4 + 0) * 132 + r0i] = vw0.x;
        Ws[(c40 * 4 + 1) * 132 + r0i] = vw0.y;
        Ws[(c40 * 4 + 2) * 132 + r0i] = vw0.z;
        Ws[(c40 * 4 + 3) * 132 + r0i] = vw0.w;
        Ws[(c41 * 4 + 0) * 132 + r1i] = vw1.x;
        Ws[(c41 * 4 + 1) * 132 + r1i] = vw1.y;
        Ws[(c41 * 4 + 2) * 132 + r1i] = vw1.z;
        Ws[(c41 * 4 + 3) * 132 + r1i] = vw1.w;
    };

    float acc[TM][TN];
#pragma unroll
    for (int i = 0; i < TM; ++i)
#pragma unroll
        for (int j = 0; j < TN; ++j) acc[i][j] = 0.f;

    float4 px0, px1, pw0, pw1;
    gload(px0, px1, pw0, pw1, 0);
    sts(0, px0, px1, pw0, pw1);
    __syncthreads();

    for (int kt = 0; kt < D / BK; ++kt) {
        int s = kt & 1;
        if (kt < D / BK - 1) gload(px0, px1, pw0, pw1, kt + 1);
        const float* Xs = psm + s * 2 * TS;
        const float* Ws = Xs + TS;
#pragma unroll
        for (int kk = 0; kk < BK; ++kk) {
            float a[TM], bb[TN];
#pragma unroll
            for (int i = 0; i < TM; ++i) a[i] = Xs[kk * 132 + ty * TM + i];
#pragma unroll
            for (int j = 0; j < TN; ++j) bb[j] = Ws[kk * 132 + tx * TN + j];
#pragma unroll
            for (int i = 0; i < TM; ++i)
#pragma unroll
                for (int j = 0; j < TN; ++j)
                    acc[i][j] = fmaf(a[i], bb[j], acc[i][j]);
        }
        if (kt < D / BK - 1) sts(s ^ 1, px0, px1, pw0, pw1);
        __syncthreads();
    }

    int col0 = colBase + tx * TN;
#pragma unroll
    for (int i = 0; i < TM; ++i) {
        int row = rowBase + ty * TM + i;
        float* zrow = z + (size_t)row * D + col0;
        __nv_bfloat162* hrow = reinterpret_cast<__nv_bfloat162*>(g_zh + (size_t)row * D) + (col0 >> 1);
#pragma unroll
        for (int j4 = 0; j4 < TN / 4; ++j4) {
            float4 v;
            v.x = acc[i][j4 * 4 + 0] + b[col0 + j4 * 4 + 0];
            v.y = acc[i][j4 * 4 + 1] + b[col0 + j4 * 4 + 1];
            v.z = acc[i][j4 * 4 + 2] + b[col0 + j4 * 4 + 2];
            v.w = acc[i][j4 * 4 + 3] + b[col0 + j4 * 4 + 3];
            *reinterpret_cast<float4*>(zrow + j4 * 4) = v;
            hrow[j4 * 2 + 0] = __nv_bfloat162(__float2bfloat16(v.x), __float2bfloat16(v.y));
            hrow[j4 * 2 + 1] = __nv_bfloat162(__float2bfloat16(v.z), __float2bfloat16(v.w));
        }
    }
}

// ============================================================================
// Kernel 2: distance GEMM on HMMA, 1-term (dot = zh.eh).
// CTA 64 rows x 128 codes, 4 warps 2(m) x 2(n), warp tile 32x64, 4 CTAs/SM.
// BK=64, 2-stage ring + intra-kt register fragment double buffering.
// ============================================================================
__global__ __launch_bounds__(128, 4)
void dist_mma_kernel(int Kcodes) {
    extern __shared__ __align__(16) char smem[];
    const uint32_t smBase = smem_to_u32(smem);

    const int tid = threadIdx.x, lane = tid & 31, wid = tid >> 5;
    const int wm = wid >> 1, wn = wid & 1;        // 2 x 2 warp grid
    const int rowBase = blockIdx.x * 64;
    const int codeBase = blockIdx.y * 128;

    const int q = lane >> 3, i8 = lane & 7;
    const uint32_t aOff = (uint32_t)(((wm * 32 + (q & 1) * 8 + i8) * SB + (q >> 1) * 8) * 2);
    const uint32_t bOff = (uint32_t)(((wn * 64 + (q >> 1) * 8 + i8) * SB + (q & 1) * 8) * 2);

    float acc[2][8][4];
#pragma unroll
    for (int mt = 0; mt < 2; ++mt)
#pragma unroll
        for (int nt = 0; nt < 8; ++nt)
#pragma unroll
            for (int e = 0; e < 4; ++e) acc[mt][nt][e] = 0.f;

    auto stage = [&](int buf, int kt) {
        uint32_t base = smBase + (uint32_t)buf * STAGEB;
        int kc = kt * 64;
#pragma unroll
        for (int i = 0; i < 12; ++i) {
            int c = tid + i * 128;              // 0..1535
            if (c < 512) {
                int hf = c & 7, r = c >> 3;     // zh row 0..63
                cp16(base + (uint32_t)(r * (SB * 2) + hf * 16),
                     g_zh + (size_t)(rowBase + r) * D + kc + hf * 8);
            } else {
                int cc = c - 512;
                int hf = cc & 7, r = cc >> 3;   // eh row 0..127
                cp16(base + ATILEB + (uint32_t)(r * (SB * 2) + hf * 16),
                     g_cbh + (size_t)(codeBase + r) * D + kc + hf * 8);
            }
        }
        asm volatile("cp.async.commit_group;" ::: "memory");
    };

    auto load_frags = [&](uint32_t* ah, uint32_t (*bfr)[2], uint32_t tb, int kh) {
#pragma unroll
        for (int mt = 0; mt < 2; ++mt)
            ldsm_x4(ah[mt * 4 + 0], ah[mt * 4 + 1], ah[mt * 4 + 2], ah[mt * 4 + 3],
                    tb + aOff + (uint32_t)(mt * 16 * SB * 2 + kh * 32));
#pragma unroll
        for (int nt2 = 0; nt2 < 4; ++nt2) {
            uint32_t r0, r1, r2, r3;
            ldsm_x4(r0, r1, r2, r3,
                    tb + ATILEB + bOff + (uint32_t)(nt2 * 16 * SB * 2 + kh * 32));
            bfr[nt2 * 2 + 0][0] = r0; bfr[nt2 * 2 + 0][1] = r1;
            bfr[nt2 * 2 + 1][0] = r2; bfr[nt2 * 2 + 1][1] = r3;
        }
    };

    auto mma_all = [&](uint32_t* ah, uint32_t (*bfr)[2]) {
#pragma unroll
        for (int mt = 0; mt < 2; ++mt)
#pragma unroll
            for (int nt = 0; nt < 8; ++nt)
                mma16816(acc[mt][nt], ah[mt * 4 + 0], ah[mt * 4 + 1],
                         ah[mt * 4 + 2], ah[mt * 4 + 3],
                         bfr[nt][0], bfr[nt][1]);
    };

    stage(0, 0);

    uint32_t ahF[2][8];
    uint32_t bfF[2][8][2];

#pragma unroll
    for (int kt = 0; kt < 4; ++kt) {
        asm volatile("cp.async.wait_group 0;" ::: "memory");
        __syncthreads();                 // publish buf kt; retire reads of the other buf
        if (kt < 3) stage((kt + 1) & 1, kt + 1);

        uint32_t tb = smBase + (uint32_t)(kt & 1) * STAGEB;

        load_frags(ahF[0], bfF[0], tb, 0);
        load_frags(ahF[1], bfF[1], tb, 1);  mma_all(ahF[0], bfF[0]);
        load_frags(ahF[0], bfF[0], tb, 2);  mma_all(ahF[1], bfF[1]);
        load_frags(ahF[1], bfF[1], tb, 3);  mma_all(ahF[0], bfF[0]);
        mma_all(ahF[1], bfF[1]);
    }

    // ---- epilogue: d = cn - 2*dot, per-row top-2 over this CTA's 128 codes ----
    __syncthreads();                      // mainloop smem dead; alias as red[]
    float4 (*red)[2] = reinterpret_cast<float4(*)[2]>(smem);

    const int g = lane >> 2;
    const int cb0 = codeBase + wn * 64 + (lane & 3) * 2;
    float cn8[8][2];
#pragma unroll
    for (int nt = 0; nt < 8; ++nt) {
        cn8[nt][0] = __ldg(&g_cn[cb0 + nt * 8 + 0]);
        cn8[nt][1] = __ldg(&g_cn[cb0 + nt * 8 + 1]);
    }
#pragma unroll
    for (int mt = 0; mt < 2; ++mt)
#pragma unroll
        for (int h = 0; h < 2; ++h) {
            float v0 = CUDART_INF_F, v1 = CUDART_INF_F;
            int i0 = 0, i1 = 0;
#pragma unroll
            for (int nt = 0; nt < 8; ++nt)
#pragma unroll
                for (int e = 0; e < 2; ++e) {
                    float dd = fmaf(-2.f, acc[mt][nt][h * 2 + e], cn8[nt][e]);
                    int code = cb0 + nt * 8 + e;
                    if (dd < v0) { v1 = v0; i1 = i0; v0 = dd; i0 = code; }
                    else if (dd < v1) { v1 = dd; i1 = code; }
                }
#pragma unroll
            for (int off = 1; off <= 2; off <<= 1) {
                float w0 = __shfl_xor_sync(0xffffffffu, v0, off);
                float w1 = __shfl_xor_sync(0xffffffffu, v1, off);
                int j0 = __shfl_xor_sync(0xffffffffu, i0, off);
                int j1 = __shfl_xor_sync(0xffffffffu, i1, off);
                top2_merge(v0, i0, v1, i1, w0, j0, w1, j1);
            }
            if ((lane & 3) == 0)
                red[wm * 32 + mt * 16 + h * 8 + g][wn] =
                    make_float4(v0, __int_as_float(i0), v1, __int_as_float(i1));
        }
    __syncthreads();

    if (tid < 64) {
        float4 p0 = red[tid][0];
        float4 p1 = red[tid][1];
        float v0 = p0.x, v1 = p0.z;
        int i0 = __float_as_int(p0.y), i1 = __float_as_int(p0.w);
        top2_merge(v0, i0, v1, i1, p1.x, __float_as_int(p1.y), p1.z, __float_as_int(p1.w));
        size_t slot = (size_t)(rowBase + tid) * gridDim.y + blockIdx.y;
        g_cv[slot] = make_float2(v0, v1);
        g_ci[slot] = make_int2(i0, i1);
    }
}

// ============================================================================
// Kernel 3 (fused): per-row approx top-4 + exact fp32 rescore + gather q into
// out + elementwise loss partial + LAST-BLOCK loss finalize (fenced counter;
// fixed-order tree reduce -> deterministic; counter reset for graph replay).
// ============================================================================
__global__ __launch_bounds__(256)
void rescore_gather_kernel(float* __restrict__ out,
                           const float* __restrict__ cb, int NT,
                           int out_size, float inv_count) {
    __shared__ float wloss[8];
    __shared__ unsigned int s_rank;
    int warp = threadIdx.x >> 5;
    int row = blockIdx.x * 8 + warp;
    int lane = threadIdx.x & 31;

    float vv[4] = { CUDART_INF_F, CUDART_INF_F, CUDART_INF_F, CUDART_INF_F };
    int ii[4] = { 0x7fffffff, 0x7fffffff, 0x7fffffff, 0x7fffffff };
    if (lane < NT) {
        float2 cv = g_cv[(size_t)row * NT + lane];
        int2 ci = g_ci[(size_t)row * NT + lane];
        vv[0] = cv.x; ii[0] = ci.x;
        vv[1] = cv.y; ii[1] = ci.y;
    }
    if (lane + 32 < NT) {
        float2 cv = g_cv[(size_t)row * NT + lane + 32];
        int2 ci = g_ci[(size_t)row * NT + lane + 32];
        vv[2] = cv.x; ii[2] = ci.x;
        vv[3] = cv.y; ii[3] = ci.y;
    }

    int jj[4];
#pragma unroll
    for (int r = 0; r < 4; ++r) {
        float bv = CUDART_INF_F; int bi = 0x7fffffff;
#pragma unroll
        for (int k = 0; k < 4; ++k)
            if (vv[k] < bv || (vv[k] == bv && ii[k] < bi)) { bv = vv[k]; bi = ii[k]; }
#pragma unroll
        for (int off = 16; off > 0; off >>= 1) {
            float wv = __shfl_xor_sync(0xffffffffu, bv, off);
            int wi = __shfl_xor_sync(0xffffffffu, bi, off);
            if (wv < bv || (wv == bv && wi < bi)) { bv = wv; bi = wi; }
        }
        jj[r] = (bi == 0x7fffffff) ? 0 : bi;
#pragma unroll
        for (int k = 0; k < 4; ++k)
            if (ii[k] == bi) { vv[k] = CUDART_INF_F; ii[k] = 0x7fffffff; }
    }

    float4* zr = reinterpret_cast<float4*>(out + (size_t)row * D);
    float4 z0 = zr[lane], z1 = zr[lane + 32];
    float s4[4];
#pragma unroll
    for (int j = 0; j < 4; ++j) {
        const float4* ej = reinterpret_cast<const float4*>(cb + (size_t)jj[j] * D);
        float4 a = ej[lane];
        float4 c = ej[lane + 32];
        float s = 0.f;
        s = fmaf(z0.x, a.x, s); s = fmaf(z0.y, a.y, s);
        s = fmaf(z0.z, a.z, s); s = fmaf(z0.w, a.w, s);
        s = fmaf(z1.x, c.x, s); s = fmaf(z1.y, c.y, s);
        s = fmaf(z1.z, c.z, s); s = fmaf(z1.w, c.w, s);
        s4[j] = s;
    }
#pragma unroll
    for (int off = 16; off > 0; off >>= 1) {
#pragma unroll
        for (int j = 0; j < 4; ++j)
            s4[j] += __shfl_xor_sync(0xffffffffu, s4[j], off);
    }
    float best = CUDART_INF_F; int bi = 0x7fffffff;
#pragma unroll
    for (int j = 0; j < 4; ++j) {
        float dj = g_cn[jj[j]] - 2.f * s4[j];
        if (dj < best || (dj == best && jj[j] < bi)) { best = dj; bi = jj[j]; }
    }

    const float4* ew = reinterpret_cast<const float4*>(cb + (size_t)bi * D);
    float ls = 0.f;
    {
        float4 qv = ew[lane];
        zr[lane] = qv;
        float dx = z0.x - qv.x, dy = z0.y - qv.y;
        float dz = z0.z - qv.z, dw = z0.w - qv.w;
        ls += dx * dx + dy * dy + dz * dz + dw * dw;
        qv = ew[lane + 32];
        zr[lane + 32] = qv;
        dx = z1.x - qv.x; dy = z1.y - qv.y;
        dz = z1.z - qv.z; dw = z1.w - qv.w;
        ls += dx * dx + dy * dy + dz * dz + dw * dw;
    }
#pragma unroll
    for (int off = 16; off > 0; off >>= 1)
        ls += __shfl_xor_sync(0xffffffffu, ls, off);
    if (lane == 0) wloss[warp] = ls;
    __syncthreads();
    if (threadIdx.x == 0) {
        float t = 0.f;
#pragma unroll
        for (int w = 0; w < 8; ++w) t += wloss[w];
        g_part[blockIdx.x] = t;
        __threadfence();
        s_rank = atomicAdd(&g_cnt, 1u);
    }
    __syncthreads();

    // last block: fixed-order tree reduce of all partials -> loss scalars
    if (s_rank == NLOSSBLK - 1) {
        __shared__ float sr[256];
        int t = threadIdx.x;
        float s = 0.f;
#pragma unroll
        for (int p = 0; p < NLOSSBLK / 256; ++p) s += g_part[t + p * 256];
        sr[t] = s;
        __syncthreads();
        for (int st = 128; st > 0; st >>= 1) {
            if (t < st) sr[t] += sr[t + st];
            __syncthreads();
        }
        if (t == 0) {
            float m = sr[0] * inv_count;
            out[out_size - 2] = m;
            out[out_size - 1] = m;
            g_cnt = 0;                    // reset for next graph replay
        }
    }
}

// ============================================================================
extern "C" void kernel_launch(void* const* d_in, const int* in_sizes, int n_in,
                              void* d_out, int out_size) {
    const float* x  = (const float*)d_in[0];
    const float* W  = (const float*)d_in[1];
    const float* b  = (const float*)d_in[2];
    const float* cb = (const float*)d_in[3];

    int M      = in_sizes[0] / D;   // 32768
    int Kcodes = in_sizes[3] / D;   // 8192
    int NT     = Kcodes / 128;      // 64
    float* out = (float*)d_out;

    cudaFuncSetAttribute(dist_mma_kernel,
                         cudaFuncAttributeMaxDynamicSharedMemorySize, DIST_SMEM);
    cudaFuncSetAttribute(proj_cnsplit_kernel,
                         cudaFuncAttributeMaxDynamicSharedMemorySize, PROJ_SMEM);

    // 1. fused projection + codebook norms/split (overlapped in one launch)
    dim3 pg(M / BM, 3);
    proj_cnsplit_kernel<<<pg, NTHREADS, PROJ_SMEM>>>(x, W, b, cb, out);

    // 2. HMMA distance GEMM (1-term, CTA 64x128, 4 CTAs/SM, frag pipelined)
    dist_mma_kernel<<<dim3(M / 64, NT), 128, DIST_SMEM>>>(Kcodes);

    // 3. fused top-4 select + exact rescore + gather + loss (incl. finalize)
    rescore_gather_kernel<<<M / 8, 256>>>(out, cb, NT, out_size,
                                          1.0f / (float)(M * D));
}